// round 17
// baseline (speedup 1.0000x reference)
#include <cuda_runtime.h>
#include <cuda_fp16.h>
#include <math.h>
#include <stdint.h>

#define S    256
#define SB   255
#define B    4096
#define H    256
#define MM   20
#define G4   1024
#define KSP  320        // static K padded to 5*64 (rows 277..319 zero)
#define WROWS 576       // 320 static + 256 dyn
#define NCTA 256
#define NGRP 32
#define GRP  8

// ---------------- scratch (static device globals; total ~1.74GB) ----------------
__device__ __align__(256) __half g_Tf[(size_t)SB*256*256*16];   // [t][tile][tid][slot] frag layout
__device__ __align__(256) __half g_Ah[(size_t)SB*32*KSP*128];   // [t][bt][k][128 swz]
__device__ __align__(256) __half g_Hh[(size_t)SB*32*H*128];     // [t][bt][j][128 swz]
__device__ __align__(256) __half g_Wh[(size_t)8*WROWS*128];     // [ntb][k][128 swz]
// fine-grained producer counters: [bt][chunk] monotonic, 128B strided
__device__ __align__(256) int g_fc[NGRP * 4 * 32];

// ---- fast-but-accurate transcendentals (MUFU EX2 + RCP; ~1e-6 rel err) ----
__device__ __forceinline__ float fexp2_(float x) {
    float r; asm("ex2.approx.ftz.f32 %0, %1;" : "=f"(r) : "f"(x)); return r;
}
__device__ __forceinline__ float frcp_(float x) {
    float r; asm("rcp.approx.ftz.f32 %0, %1;" : "=f"(r) : "f"(x)); return r;
}
#define LOG2E 1.4426950408889634f
__device__ __forceinline__ float sigmoidf_(float x) {
    return frcp_(1.f + fexp2_(-x * LOG2E));
}
__device__ __forceinline__ float tanhf_(float x) {
    return 1.f - 2.f * frcp_(1.f + fexp2_(2.f * x * LOG2E));
}

__device__ __forceinline__ uint32_t smem_u32(const void* p) {
    uint32_t a;
    asm("{ .reg .u64 t; cvta.to.shared.u64 t, %1; cvt.u32.u64 %0, t; }" : "=r"(a) : "l"(p));
    return a;
}
__device__ __forceinline__ void ldsm4t(uint32_t* r, uint32_t addr) {
    asm volatile("ldmatrix.sync.aligned.m8n8.x4.trans.shared.b16 {%0,%1,%2,%3}, [%4];"
        : "=r"(r[0]), "=r"(r[1]), "=r"(r[2]), "=r"(r[3]) : "r"(addr));
}
__device__ __forceinline__ void mma_f16(float* d, const uint32_t* a, const uint32_t* b) {
    asm volatile("mma.sync.aligned.m16n8k16.row.col.f32.f16.f16.f32 "
        "{%0,%1,%2,%3}, {%4,%5,%6,%7}, {%8,%9}, {%0,%1,%2,%3};"
        : "+f"(d[0]), "+f"(d[1]), "+f"(d[2]), "+f"(d[3])
        : "r"(a[0]), "r"(a[1]), "r"(a[2]), "r"(a[3]), "r"(b[0]), "r"(b[1]));
}
__device__ __forceinline__ void bulkcp(uint32_t dst, const void* src, uint32_t n, uint32_t mbar) {
    asm volatile("cp.async.bulk.shared::cta.global.mbarrier::complete_tx::bytes [%0], [%1], %2, [%3];"
        :: "r"(dst), "l"(src), "r"(n), "r"(mbar) : "memory");
}
#define MBARRIER_INIT(a, c) \
    asm volatile("mbarrier.init.shared.b64 [%0], %1;" :: "r"((uint32_t)(a)), "r"((uint32_t)(c)) : "memory")
#define MBARRIER_EXPECT_TX(a, n) \
    asm volatile("mbarrier.arrive.expect_tx.shared.b64 _, [%0], %1;" :: "r"((uint32_t)(a)), "r"((uint32_t)(n)) : "memory")
#define MBARRIER_WAIT_PARITY(a, ph) do { \
    uint32_t _m = (uint32_t)(a), _p = (uint32_t)(ph), _d; \
    asm volatile("{\n\t.reg .pred p;\n\t" \
        "mbarrier.try_wait.parity.acquire.cta.shared::cta.b64 p, [%1], %2;\n\t" \
        "selp.b32 %0, 1, 0, p;\n\t}" : "=r"(_d) : "r"(_m), "r"(_p) : "memory"); \
    if (!_d) { \
        asm volatile("{\n\t.reg .pred P1;\n\t" \
            "WL_%=:\n\t" \
            "mbarrier.try_wait.parity.acquire.cta.shared::cta.b64 P1, [%0], %1, 0x989680;\n\t" \
            "@P1 bra.uni WD_%=;\n\t" \
            "bra.uni WL_%=;\n\t" \
            "WD_%=:\n\t}" :: "r"(_m), "r"(_p) : "memory"); \
    } \
} while (0)

// k_seq stage: A 16K + Bh 16K, 3-stage ring
#define OFF_A  0
#define OFF_BH 16384
#define SEQ_STAGE 32768
#define SEQ_NSTG  3
#define SEQ_SMEM  (SEQ_NSTG * SEQ_STAGE)  // 98304

// ============================================================
// k_packw: weights -> [ntb][k][128 swz] fp16; resets fine counters.
// rows: 0-19 W_x_p | 20-275 W_s_p | 276 bias | 277-319 zero | 320-575 W_h_p
// ============================================================
__global__ void k_packw(const float* __restrict__ W_x_p, const float* __restrict__ W_h_p,
                        const float* __restrict__ W_s_p, const float* __restrict__ b_p)
{
    int idx = blockIdx.x * blockDim.x + threadIdx.x;
    if (idx < NGRP * 4 * 32) g_fc[idx] = 0;
    if (idx >= 8 * WROWS * 128) return;
    int tile = idx / (WROWS * 128);
    int rem  = idx % (WROWS * 128);
    int k    = rem >> 7;
    int col  = rem & 127;
    int np = tile * 128 + col;
    int j = np >> 2, g = np & 3;
    int scol = g * H + j;
    float v;
    if (k < MM)            v = W_x_p[(size_t)k * G4 + scol];
    else if (k < MM + H)   v = W_s_p[(size_t)(k - MM) * G4 + scol];
    else if (k == 276)     v = b_p[scol];
    else if (k < KSP)      v = 0.f;
    else                   v = W_h_p[(size_t)(k - KSP) * G4 + scol];
    int u = col >> 3, e = col & 7;
    g_Wh[((size_t)tile * WROWS + k) * 128 + (((u ^ (k & 7)) << 3) + e)] = __float2half(v);
}

// ============================================================
// k_pre: T into frag layout g_Tf; static A rows into swizzled tiled g_Ah
// grid (SB, B/64), block 256
// ============================================================
__global__ void k_pre(const float* __restrict__ val_seq, const float* __restrict__ delta,
                      const float* __restrict__ W_d,  const float* __restrict__ b_d,
                      const float* __restrict__ W_xt, const float* __restrict__ W_dt,
                      const float* __restrict__ b_t,
                      const float* __restrict__ W_x_s, const float* __restrict__ b_s)
{
    __shared__ float sx[64][20];
    __shared__ float sde[64][32];
    __shared__ float sT[256][16];
    __shared__ float sH[256][16];
    int t = blockIdx.x;
    int b0 = blockIdx.y * 64;
    int bt = b0 >> 7;
    int tid = threadIdx.x;
    size_t abase = ((size_t)t * 32 + bt) * KSP * 128;

    for (int e = tid; e < 64 * 20; e += 256) {
        int b = e / 20, k = e % 20;
        sx[b][k] = val_seq[((size_t)t * B + b0 + b) * MM + k];
    }
    for (int e = tid; e < 64 * 32; e += 256) {
        int b = e >> 5, ee = e & 31;
        float dd = delta[(size_t)t * B + b0 + b];
        sde[b][ee] = tanhf_(dd * W_d[ee] + b_d[ee]);
    }
    __syncthreads();

    int j = tid;
    float wxt[20], wdt[32], wi[20], wo[20], wg[20];
    #pragma unroll
    for (int k = 0; k < 20; k++) wxt[k] = W_xt[k * H + j];
    #pragma unroll
    for (int e = 0; e < 32; e++) wdt[e] = W_dt[e * H + j];
    #pragma unroll
    for (int k = 0; k < 20; k++) {
        wi[k] = W_x_s[k * G4 + j];
        wo[k] = W_x_s[k * G4 + 2 * H + j];
        wg[k] = W_x_s[k * G4 + 3 * H + j];
    }
    float bt_ = b_t[j], bi = b_s[j], bo = b_s[2 * H + j], bg = b_s[3 * H + j];

    for (int bc = 0; bc < 4; bc++) {
        #pragma unroll 1
        for (int bl = 0; bl < 16; bl++) {
            int b = bc * 16 + bl;
            float tx = bt_, td = 0.f, ai = bi, ao = bo, ag = bg;
            #pragma unroll
            for (int k = 0; k < 20; k++) {
                float xv = sx[b][k];
                tx += xv * wxt[k]; ai += xv * wi[k]; ao += xv * wo[k]; ag += xv * wg[k];
            }
            #pragma unroll
            for (int e = 0; e < 32; e++) td += sde[b][e] * wdt[e];
            float T = sigmoidf_(tx + sigmoidf_(td));
            float cns = sigmoidf_(ai) * T * tanhf_(ag);
            sT[j][bl] = T;
            sH[j][bl] = sigmoidf_(ao) * tanhf_(cns);
        }
        __syncthreads();
        for (int e = tid; e < 256 * 16; e += 256) {
            int jj = e >> 4, bl = e & 15;
            int b_local = (b0 & 127) + bc * 16 + bl;
            {
                int tile = bt * 8 + (jj >> 5);
                int wn = (jj >> 4) & 1, j_in = jj & 15, nt = j_in >> 1, cpair = j_in & 1;
                int wm = b_local >> 5, r = b_local & 31;
                int mf = r >> 4, oddb = (r >> 3) & 1, r_lane = r & 7;
                int tidt = ((wn << 2) | wm) * 32 + (oddb | (cpair << 1) | (r_lane << 2));
                int slot = mf * 8 + nt;
                g_Tf[(((size_t)t * 256 + tile) * 256 + tidt) * 16 + slot] = __float2half(sT[jj][bl]);
            }
            int k = 20 + jj;
            int u = b_local >> 3, ee = b_local & 7;
            g_Ah[abase + (size_t)k * 128 + (((u ^ (k & 7)) << 3) + ee)] = __float2half(sH[jj][bl]);
        }
        for (int e = tid; e < 20 * 16; e += 256) {
            int k = e >> 4, bl = e & 15;
            int b_local = (b0 & 127) + bc * 16 + bl;
            int u = b_local >> 3, ee = b_local & 7;
            g_Ah[abase + (size_t)k * 128 + (((u ^ (k & 7)) << 3) + ee)] = __float2half(sx[bc * 16 + bl][k]);
        }
        __syncthreads();
    }
    if (tid < 64) {
        int b_local = (b0 & 127) + tid;
        int u = b_local >> 3, ee = b_local & 7;
        g_Ah[abase + (size_t)276 * 128 + (((u ^ 4) << 3) + ee)] = __float2half(1.f);
    }
}

// ============================================================
// k_seq: persistent recurrence; fine-grained per-(bt,chunk) producer counters.
// Producer (tid32): S2G h -> membar.gl -> atomicAdd counter[bt][ntb>>1].
// Consumer (tid0): per dyn chunk c, spin counter[bt][c] >= 2(t+1), then issue A.
// Static GEMM for t+1 fills the pipeline while producers publish.
// ============================================================
__global__ void __launch_bounds__(256, 2) k_seq()
{
    extern __shared__ __align__(16) char sm[];
    __shared__ __align__(8) unsigned long long mbar[SEQ_NSTG];
    __shared__ __align__(16) __half hstage[32 * 128];   // 8KB h staging
    int clin = blockIdx.x;
    int bt = clin >> 3, ntb = clin & 7;
    int tid = threadIdx.x, lane = tid & 31, wid = tid >> 5;
    int wm = wid & 3, wn = wid >> 2;
    uint32_t smb = smem_u32(sm);
    uint32_t hsb = smem_u32(hstage);
    uint32_t mb[SEQ_NSTG];
    #pragma unroll
    for (int i = 0; i < SEQ_NSTG; i++) mb[i] = smem_u32(&mbar[i]);
    if (tid == 0) {
        #pragma unroll
        for (int i = 0; i < SEQ_NSTG; i++) MBARRIER_INIT(mb[i], 1);
    }
    __syncthreads();
    uint32_t ph[SEQ_NSTG] = {0, 0, 0};
    int gq = 0;   // running chunk counter (stage = gq % 3)

    const __half* Wbase = g_Wh + (size_t)ntb * WROWS * 128;
    volatile int* fc = (volatile int*)&g_fc[bt * 4 * 32];

    int kra = (lane >> 4) * 8 + (lane & 7);
    int ua0 = ((lane >> 3) & 1) + wm * 4;
    int swa = kra & 7;
    int krb = (lane & 7) + ((lane >> 3) & 1) * 8;
    int ub0 = (lane >> 4) + wn * 8;
    int swb = krb & 7;
    uint32_t aoff0 = (uint32_t)(kra * 256);
    uint32_t boff0 = (uint32_t)(krb * 256);

    float acc[2][8][4];
    float* afl = &acc[0][0][0];
    float c_reg[16];
    #pragma unroll
    for (int i = 0; i < 16; i++) c_reg[i] = 0.f;

    int odd = lane & 1, cpair = (lane >> 1) & 1, r_lane = lane >> 2;

    auto finewait = [&](int c, int t) {   // wait for h[t] rows of dyn chunk c
        while (fc[c * 32] < 2 * (t + 1)) __nanosleep(32);
    };
    auto issue_full = [&](int stg, const __half* aSrc, int wrow, uint32_t abytes, uint32_t bbytes) {
        if (tid == 0) {
            MBARRIER_EXPECT_TX(mb[stg], abytes + bbytes);
            uint32_t d = smb + (uint32_t)stg * SEQ_STAGE;
            bulkcp(d + OFF_A,  aSrc,                       abytes, mb[stg]);
            bulkcp(d + OFF_BH, Wbase + (size_t)wrow * 128, bbytes, mb[stg]);
        }
    };
    auto compute_chunk = [&](int stg, int nkf) {
        uint32_t sb = smb + (uint32_t)stg * SEQ_STAGE;
        #pragma unroll 4
        for (int kf = 0; kf < nkf; kf++) {
            uint32_t kofs = (uint32_t)(kf * 4096);
            uint32_t ah[2][4], bh[4][4];
            #pragma unroll
            for (int mf = 0; mf < 2; mf++)
                ldsm4t(ah[mf], sb + OFF_A + aoff0 + kofs + (uint32_t)(((ua0 + mf * 2) ^ swa) << 4));
            #pragma unroll
            for (int nf = 0; nf < 4; nf++)
                ldsm4t(bh[nf], sb + OFF_BH + boff0 + kofs + (uint32_t)(((ub0 + nf * 2) ^ swb) << 4));
            #pragma unroll
            for (int mf = 0; mf < 2; mf++)
                #pragma unroll
                for (int nf = 0; nf < 4; nf++) {
                    mma_f16(acc[mf][2 * nf],     ah[mf], bh[nf]);
                    mma_f16(acc[mf][2 * nf + 1], ah[mf], bh[nf] + 2);
                }
        }
    };

    // dyn GEMM: stages for chunks 0-2 pre-staged by stage_next_dyn; chunk 3 in-loop
    auto run_dyn = [&](const __half* Ad, int tprev) {
        for (int c = 0; c < 4; c++) {
            int stg = (gq + c) % SEQ_NSTG;
            MBARRIER_WAIT_PARITY(mb[stg], ph[stg]); ph[stg] ^= 1;
            compute_chunk(stg, 4);
            __syncthreads();
            if (c == 0 && tid == 0) {
                finewait(3, tprev);
                issue_full((gq + 3) % SEQ_NSTG, Ad + (size_t)3 * 64 * 128, KSP + 192, 16384, 16384);
            }
        }
        gq += 4;
    };
    // static GEMM: 5 chunks, chunk 4 trimmed to 2 kf / 8KB copies
    auto run_static = [&](const __half* A0) {
        for (int c = 0; c < 3; c++)
            issue_full((gq + c) % SEQ_NSTG, A0 + (size_t)c * 64 * 128, c * 64, 16384, 16384);
        for (int c = 0; c < 5; c++) {
            int stg = (gq + c) % SEQ_NSTG;
            MBARRIER_WAIT_PARITY(mb[stg], ph[stg]); ph[stg] ^= 1;
            compute_chunk(stg, (c == 4) ? 2 : 4);
            __syncthreads();
            if (c < 2) {
                int cc = c + 3;
                uint32_t sz = (cc == 4) ? 8192u : 16384u;
                issue_full((gq + cc) % SEQ_NSTG, A0 + (size_t)cc * 64 * 128, cc * 64, sz, sz);
            }
        }
        gq += 5;
    };

    auto epilogue = [&](int t, const __half* tv) {
        #pragma unroll
        for (int mf = 0; mf < 2; mf++) {
            int b_local = wm * 32 + mf * 16 + r_lane + (odd ? 8 : 0);
            #pragma unroll
            for (int nt = 0; nt < 8; nt++) {
                float d0 = acc[mf][nt][0], d1 = acc[mf][nt][1];
                float d2 = acc[mf][nt][2], d3 = acc[mf][nt][3];
                float s1 = odd ? d0 : d2;
                float s2 = odd ? d1 : d3;
                float r1 = __shfl_xor_sync(0xffffffffu, s1, 1);
                float r2 = __shfl_xor_sync(0xffffffffu, s2, 1);
                float fi = odd ? r1 : d0;
                float ff = odd ? r2 : d1;
                float fo = odd ? d2 : r1;
                float fg = odd ? d3 : r2;
                int slot = mf * 8 + nt;
                float T = __half2float(tv[slot]);
                float cn = sigmoidf_(ff) * c_reg[slot] + sigmoidf_(fi) * T * tanhf_(fg);
                c_reg[slot] = cn;
                float h = sigmoidf_(fo) * tanhf_(cn);
                int j_local = wn * 16 + nt * 2 + cpair;
                hstage[j_local * 128 + (((b_local >> 3) ^ (j_local & 7)) << 3) + (b_local & 7)]
                    = __float2half(h);
            }
        }
        __syncthreads();
    };
    // publisher (tid 32): S2G h, then release via fine counter
    auto publish = [&](int t, bool doArrive) {
        if (tid == 32) {
            asm volatile("fence.proxy.async.shared::cta;" ::: "memory");
            const __half* gdst = g_Hh + (((size_t)t * 32 + bt) * H + ntb * 32) * 128;
            asm volatile("cp.async.bulk.global.shared::cta.bulk_group [%0], [%1], %2;"
                :: "l"(gdst), "r"(hsb), "r"(8192u) : "memory");
            asm volatile("cp.async.bulk.commit_group;" ::: "memory");
            asm volatile("cp.async.bulk.wait_group 0;" ::: "memory");
            if (doArrive) {
                asm volatile("membar.gl;" ::: "memory");
                atomicAdd(&g_fc[(bt * 4 + (ntb >> 1)) * 32], 1);
            }
        }
    };
    // stage dyn chunks 0-2 for step t+1: B immediately; A as producers land
    auto stage_next_dyn = [&](int t) {
        if (tid == 0) {
            #pragma unroll
            for (int c = 0; c < 3; c++) {
                int stg = (gq + c) % SEQ_NSTG;
                MBARRIER_EXPECT_TX(mb[stg], 32768u);
                bulkcp(smb + (uint32_t)stg * SEQ_STAGE + OFF_BH,
                       Wbase + (size_t)(KSP + c * 64) * 128, 16384, mb[stg]);
            }
            const __half* Ad = g_Hh + ((size_t)t * 32 + bt) * H * 128;
            #pragma unroll
            for (int c = 0; c < 3; c++) {
                finewait(c, t);
                bulkcp(smb + (uint32_t)((gq + c) % SEQ_NSTG) * SEQ_STAGE + OFF_A,
                       Ad + (size_t)c * 64 * 128, 16384, mb[(gq + c) % SEQ_NSTG]);
            }
        }
    };

    // ---- prologue: static(0) ----
    #pragma unroll
    for (int i = 0; i < 64; i++) afl[i] = 0.f;
    run_static(g_Ah + (size_t)bt * KSP * 128);

    // ---- t = 0 ----
    {
        uint4 traw[2];
        const uint4* tp = (const uint4*)(g_Tf + ((size_t)clin * 256 + tid) * 16);
        traw[0] = tp[0]; traw[1] = tp[1];
        epilogue(0, (const __half*)traw);
        publish(0, true);
        #pragma unroll
        for (int i = 0; i < 64; i++) afl[i] = 0.f;
        run_static(g_Ah + ((size_t)1 * 32 + bt) * KSP * 128);
        stage_next_dyn(0);
    }

    for (int t = 1; t < SB; t++) {
        uint4 traw[2];
        const uint4* tp = (const uint4*)(g_Tf + (((size_t)t * 256 + clin) * 256 + tid) * 16);
        traw[0] = tp[0]; traw[1] = tp[1];

        run_dyn(g_Hh + ((size_t)(t - 1) * 32 + bt) * H * 128, t - 1);
        epilogue(t, (const __half*)traw);
        publish(t, t + 1 < SB);

        if (t + 1 >= SB) break;
        #pragma unroll
        for (int i = 0; i < 64; i++) afl[i] = 0.f;
        run_static(g_Ah + ((size_t)(t + 1) * 32 + bt) * KSP * 128);
        stage_next_dyn(t);
    }
}

// ============================================================
// k_out: output heads; reads swizzled tiled g_Hh
// ============================================================
__global__ void k_out(const float* __restrict__ Wc, const float* __restrict__ bc,
                      const float* __restrict__ Wm, const float* __restrict__ bm,
                      float* __restrict__ out)
{
    __shared__ float sh[256][32];
    __shared__ float sl[32][25];
    int t = blockIdx.x;
    int b0 = blockIdx.y * 32;
    int bt = b0 >> 7;
    int tid = threadIdx.x;

    for (int e = tid; e < 256 * 32; e += 256) {
        int jj = e >> 5, bb = e & 31;
        int b_local = (b0 & 127) + bb;
        int u = b_local >> 3, ee = b_local & 7;
        sh[jj][bb] = __half2float(
            g_Hh[(((size_t)t * 32 + bt) * H + jj) * 128 + (((u ^ (jj & 7)) << 3) + ee)]);
    }
    __syncthreads();

    for (int o = tid; o < 32 * 25; o += 256) {
        int r = o / 25, jx = o % 25;
        float s;
        if (jx < 3) {
            s = bc[jx];
            #pragma unroll 8
            for (int k = 0; k < H; k++) s += sh[k][r] * Wc[k * 3 + jx];
        } else {
            int jj = jx - 3;
            s = bm[jj];
            #pragma unroll 8
            for (int k = 0; k < H; k++) s += sh[k][r] * Wm[k * 22 + jj];
        }
        sl[r][jx] = s;
    }
    __syncthreads();

    float* out_cat = out;
    float* out_val = out + (size_t)SB * B * 3;
    for (int o = tid; o < 32 * 25; o += 256) {
        int r = o / 25, jx = o % 25;
        int b = b0 + r;
        if (jx < 3) {
            float l0 = sl[r][0], l1 = sl[r][1], l2 = sl[r][2];
            float mx = fmaxf(l0, fmaxf(l1, l2));
            float e0 = fexp2_((l0 - mx) * LOG2E);
            float e1 = fexp2_((l1 - mx) * LOG2E);
            float e2 = fexp2_((l2 - mx) * LOG2E);
            float inv = frcp_(e0 + e1 + e2);
            float v = (jx == 0 ? e0 : (jx == 1 ? e1 : e2)) * inv;
            out_cat[(size_t)t * B * 3 + (size_t)b * 3 + jx] = v;
        } else {
            out_val[(size_t)t * B * 22 + (size_t)b * 22 + (jx - 3)] = sl[r][jx];
        }
    }
}

// ============================================================
// launch
// ============================================================
extern "C" void kernel_launch(void* const* d_in, const int* in_sizes, int n_in,
                              void* d_out, int out_size)
{
    const float* val_seq = (const float*)d_in[1];
    const float* delta   = (const float*)d_in[2];
    const float* W_d     = (const float*)d_in[3];
    const float* b_d     = (const float*)d_in[4];
    const float* W_xt    = (const float*)d_in[5];
    const float* W_dt    = (const float*)d_in[6];
    const float* b_t     = (const float*)d_in[7];
    const float* W_x_s   = (const float*)d_in[8];
    const float* b_s     = (const float*)d_in[10];
    const float* W_x_p   = (const float*)d_in[11];
    const float* W_h_p   = (const float*)d_in[12];
    const float* W_s_p   = (const float*)d_in[13];
    const float* b_p     = (const float*)d_in[14];
    const float* Wc      = (const float*)d_in[15];
    const float* bcv     = (const float*)d_in[16];
    const float* Wm      = (const float*)d_in[17];
    const float* bm      = (const float*)d_in[18];
    float* out = (float*)d_out;

    cudaFuncSetAttribute(k_seq, cudaFuncAttributeMaxDynamicSharedMemorySize, SEQ_SMEM);

    k_packw<<<(8 * WROWS * 128 + 255) / 256, 256>>>(W_x_p, W_h_p, W_s_p, b_p);
    k_pre<<<dim3(SB, B / 64), 256>>>(val_seq, delta, W_d, b_d, W_xt, W_dt, b_t, W_x_s, b_s);
    k_seq<<<NCTA, 256, SEQ_SMEM>>>();
    k_out<<<dim3(SB, B / 32), 256>>>(Wc, bcv, Wm, bm, out);
}